// round 4
// baseline (speedup 1.0000x reference)
#include <cuda_runtime.h>

// Shapes fixed by the problem: B=64, L=512, E=64, H=8, D=8
#define LSEQ 512
#define EDIM 64

// Scratch (static device globals — no allocation)
__device__ float g_qh[64 * 512 * 64];
__device__ float g_kh[64 * 512 * 64];
__device__ float g_vh[64 * 512 * 64];
__device__ float g_ctx[64 * 512 * 64];

// ---------------------------------------------------------------------------
// Warp helpers
// ---------------------------------------------------------------------------
__device__ __forceinline__ float warp_sum(float v) {
  #pragma unroll
  for (int off = 16; off; off >>= 1) v += __shfl_xor_sync(0xffffffffu, v, off);
  return v;
}
__device__ __forceinline__ float warp_max(float v) {
  #pragma unroll
  for (int off = 16; off; off >>= 1)
    v = fmaxf(v, __shfl_xor_sync(0xffffffffu, v, off));
  return v;
}

// ---------------------------------------------------------------------------
// Projections: out = x @ W.T + b for (q,Wq),(k,Wk),(k,Wv); blockIdx.y selects.
// Thread = (col c, slot s). W column held in REGISTERS (64/thread); x rows
// staged in SMEM, read as broadcast LDS.128 (4 dims per op). 128 rows/block.
// ---------------------------------------------------------------------------
__global__ __launch_bounds__(256) void proj_kernel(
    const float* __restrict__ q, const float* __restrict__ k,
    const float* __restrict__ Wq, const float* __restrict__ bq,
    const float* __restrict__ Wk, const float* __restrict__ bk,
    const float* __restrict__ Wv, const float* __restrict__ bv,
    float* __restrict__ qh, float* __restrict__ kh, float* __restrict__ vh) {
  __shared__ __align__(16) float Wsm[64 * 68];
  __shared__ __align__(16) float xs[128 * 68];

  int sel = blockIdx.y;
  const float* x = (sel == 0) ? q : k;
  const float* W = (sel == 0) ? Wq : (sel == 1) ? Wk : Wv;
  const float* bias = (sel == 0) ? bq : (sel == 1) ? bk : bv;
  float* out = (sel == 0) ? qh : (sel == 1) ? kh : vh;

  int tid = threadIdx.x;
  int c = tid & 63, s = tid >> 6;
  size_t row0 = (size_t)blockIdx.x * 128;

  // stage W coalesced (row-major [64][64] -> padded [64][68])
  for (int idx = tid; idx < 1024; idx += 256) {
    int r = idx >> 4, d4 = idx & 15;
    *(float4*)&Wsm[r * 68 + d4 * 4] = *(const float4*)&W[r * 64 + d4 * 4];
  }
  // stage x rows coalesced
  for (int idx = tid; idx < 2048; idx += 256) {
    int r = idx >> 4, d4 = idx & 15;
    *(float4*)&xs[r * 68 + d4 * 4] =
        *(const float4*)&x[(row0 + r) * 64 + d4 * 4];
  }
  __syncthreads();

  // pull W[c][:] into registers (padded rows -> conflict-free across lanes)
  float wr[64];
  #pragma unroll
  for (int d4 = 0; d4 < 16; d4++) {
    float4 w = *(const float4*)&Wsm[c * 68 + d4 * 4];
    wr[d4 * 4 + 0] = w.x; wr[d4 * 4 + 1] = w.y;
    wr[d4 * 4 + 2] = w.z; wr[d4 * 4 + 3] = w.w;
  }
  float bc = bias[c];

  // each slot handles 32 rows
  #pragma unroll 2
  for (int rr = 0; rr < 32; rr++) {
    int row = s * 32 + rr;
    const float4* xrow = (const float4*)&xs[row * 68];
    float a0 = 0.f, a1 = 0.f, a2 = 0.f, a3 = 0.f;
    #pragma unroll
    for (int d4 = 0; d4 < 16; d4++) {
      float4 xv = xrow[d4];  // broadcast across warp
      a0 = fmaf(xv.x, wr[d4 * 4 + 0], a0);
      a1 = fmaf(xv.y, wr[d4 * 4 + 1], a1);
      a2 = fmaf(xv.z, wr[d4 * 4 + 2], a2);
      a3 = fmaf(xv.w, wr[d4 * 4 + 3], a3);
    }
    out[(row0 + row) * 64 + c] = (a0 + a1) + (a2 + a3) + bc;
  }
}

// ---------------------------------------------------------------------------
// Attention: block = (16-query tile, batch); 8 warps, 2 queries per warp,
// lane = key phase (key m = lane + 32j). K/V staged m-major padded [512][12]
// so K[m][0..7] = 2x conflict-free LDS.128. Head-mean attention accumulates
// in REGISTERS (key ownership is head-invariant), written once at the end.
// ---------------------------------------------------------------------------
__global__ __launch_bounds__(256, 2) void attn_kernel(
    const float* __restrict__ qh, const float* __restrict__ kh,
    const float* __restrict__ vh, float* __restrict__ ctx,
    float* __restrict__ attn_out) {
  extern __shared__ float sm[];
  float* Ks = sm;             // [512][12]
  float* Vs = sm + 6144;      // [512][12]

  int b = blockIdx.y;
  int q0 = blockIdx.x * 16;
  int tid = threadIdx.x;
  int w = tid >> 5;
  int lane = tid & 31;
  int qi0 = q0 + w * 2;  // this warp's two queries

  const float scale = 0.3535533905932738f;  // 1/sqrt(8)
  const float* kbase = kh + (size_t)b * 512 * 64;
  const float* vbase = vh + (size_t)b * 512 * 64;

  float amean[2][16];
  #pragma unroll
  for (int i = 0; i < 2; i++)
    #pragma unroll
    for (int j = 0; j < 16; j++) amean[i][j] = 0.f;

  #pragma unroll 1
  for (int h = 0; h < 8; h++) {
    __syncthreads();  // prior head done with Ks/Vs
    // stage K,V for this head, m-major: idx -> (m = idx&511, half = idx>>9)
    // first 512 idx are half 0 (lanes hit distinct banks: 12m % 32)
    for (int idx = tid; idx < 1024; idx += 256) {
      int m = idx & 511, half = idx >> 9;
      int g = m * 64 + h * 8 + half * 4;
      *(float4*)&Ks[m * 12 + half * 4] = *(const float4*)(kbase + g);
      *(float4*)&Vs[m * 12 + half * 4] = *(const float4*)(vbase + g);
    }
    __syncthreads();

    // queries (pre-scaled)
    float qr[2][8];
    #pragma unroll
    for (int i = 0; i < 2; i++) {
      const float4* qp = (const float4*)(qh +
          ((size_t)(b * 512 + qi0 + i)) * 64 + h * 8);
      float4 a = qp[0], c4 = qp[1];
      qr[i][0] = a.x * scale;  qr[i][1] = a.y * scale;
      qr[i][2] = a.z * scale;  qr[i][3] = a.w * scale;
      qr[i][4] = c4.x * scale; qr[i][5] = c4.y * scale;
      qr[i][6] = c4.z * scale; qr[i][7] = c4.w * scale;
    }

    // scores
    float s[2][16];
    #pragma unroll
    for (int j = 0; j < 16; j++) {
      int m = lane + 32 * j;
      float4 k0 = *(const float4*)&Ks[m * 12];
      float4 k1 = *(const float4*)&Ks[m * 12 + 4];
      #pragma unroll
      for (int i = 0; i < 2; i++) {
        float a = qr[i][0] * k0.x;
        a = fmaf(qr[i][1], k0.y, a);
        a = fmaf(qr[i][2], k0.z, a);
        a = fmaf(qr[i][3], k0.w, a);
        a = fmaf(qr[i][4], k1.x, a);
        a = fmaf(qr[i][5], k1.y, a);
        a = fmaf(qr[i][6], k1.z, a);
        a = fmaf(qr[i][7], k1.w, a);
        s[i][j] = a;
      }
    }

    // softmax (warp-wide over 512 keys)
    float inv[2];
    #pragma unroll
    for (int i = 0; i < 2; i++) {
      float M = s[i][0];
      #pragma unroll
      for (int j = 1; j < 16; j++) M = fmaxf(M, s[i][j]);
      M = warp_max(M);
      float Z = 0.f;
      #pragma unroll
      for (int j = 0; j < 16; j++) {
        float e = __expf(s[i][j] - M);
        s[i][j] = e;
        Z += e;
      }
      Z = warp_sum(Z);
      inv[i] = 1.0f / Z;
    }

    // probabilities -> amean (regs) + ctx accumulation
    float cacc[2][8];
    #pragma unroll
    for (int i = 0; i < 2; i++)
      #pragma unroll
      for (int d = 0; d < 8; d++) cacc[i][d] = 0.f;

    #pragma unroll
    for (int j = 0; j < 16; j++) {
      int m = lane + 32 * j;
      float4 v0 = *(const float4*)&Vs[m * 12];
      float4 v1 = *(const float4*)&Vs[m * 12 + 4];
      #pragma unroll
      for (int i = 0; i < 2; i++) {
        float p = s[i][j] * inv[i];
        amean[i][j] = fmaf(0.125f, p, amean[i][j]);
        cacc[i][0] = fmaf(p, v0.x, cacc[i][0]);
        cacc[i][1] = fmaf(p, v0.y, cacc[i][1]);
        cacc[i][2] = fmaf(p, v0.z, cacc[i][2]);
        cacc[i][3] = fmaf(p, v0.w, cacc[i][3]);
        cacc[i][4] = fmaf(p, v1.x, cacc[i][4]);
        cacc[i][5] = fmaf(p, v1.y, cacc[i][5]);
        cacc[i][6] = fmaf(p, v1.z, cacc[i][6]);
        cacc[i][7] = fmaf(p, v1.w, cacc[i][7]);
      }
    }

    // reduce ctx partials across lanes
    #pragma unroll
    for (int i = 0; i < 2; i++)
      #pragma unroll
      for (int d = 0; d < 8; d++)
        cacc[i][d] = warp_sum(cacc[i][d]);

    // lane (i*8+d) writes ctx entry (static select chain)
    float val = 0.f;
    #pragma unroll
    for (int i = 0; i < 2; i++)
      #pragma unroll
      for (int d = 0; d < 8; d++)
        if ((lane >> 3) == i && (lane & 7) == d) val = cacc[i][d];
    if (lane < 16)
      ctx[((size_t)(b * 512 + qi0 + (lane >> 3))) * 64 + h * 8 + (lane & 7)] =
          val;
  }

  // write head-averaged attention from registers, coalesced (128B per j)
  #pragma unroll
  for (int i = 0; i < 2; i++) {
    float* ao = attn_out + ((size_t)(b * 512 + qi0 + i)) * 512 + lane;
    #pragma unroll
    for (int j = 0; j < 16; j++) ao[32 * j] = amean[i][j];
  }
}

// ---------------------------------------------------------------------------
// Epilogue: warp-per-row. o = ctx@Wo.T + bo + prev; x = LN1(o);
// f = relu(x@W1.T+b1)@W2.T + b2 + x; out = LN2(f)
// ---------------------------------------------------------------------------
__device__ __forceinline__ float2 matvec64(const float* __restrict__ WT,
                                           float2 v, int lane) {
  float2 o = make_float2(0.f, 0.f);
  #pragma unroll
  for (int d = 0; d < 64; d++) {
    float xd = __shfl_sync(0xffffffffu, (d & 1) ? v.y : v.x, d >> 1);
    float2 w = *(const float2*)&WT[d * 66 + 2 * lane];
    o.x = fmaf(xd, w.x, o.x);
    o.y = fmaf(xd, w.y, o.y);
  }
  return o;
}

__global__ __launch_bounds__(256) void epi_kernel(
    const float* __restrict__ ctx, const float* __restrict__ prev,
    const float* __restrict__ Wo, const float* __restrict__ bo,
    const float* __restrict__ g1, const float* __restrict__ b1ln,
    const float* __restrict__ W1, const float* __restrict__ b1,
    const float* __restrict__ W2, const float* __restrict__ b2,
    const float* __restrict__ g2, const float* __restrict__ b2ln,
    float* __restrict__ out) {
  __shared__ __align__(16) float WoT[64 * 66];
  __shared__ __align__(16) float W1T[64 * 66];
  __shared__ __align__(16) float W2T[64 * 66];

  int tid = threadIdx.x, lane = tid & 31, wid = tid >> 5;
  for (int idx = tid; idx < 4096; idx += 256) {
    int c = idx >> 6, d = idx & 63;
    WoT[d * 66 + c] = Wo[idx];
    W1T[d * 66 + c] = W1[idx];
    W2T[d * 66 + c] = W2[idx];
  }
  float2 boc = *(const float2*)&bo[2 * lane];
  float2 g1c = *(const float2*)&g1[2 * lane];
  float2 b1lc = *(const float2*)&b1ln[2 * lane];
  float2 b1c = *(const float2*)&b1[2 * lane];
  float2 b2c = *(const float2*)&b2[2 * lane];
  float2 g2c = *(const float2*)&g2[2 * lane];
  float2 b2lc = *(const float2*)&b2ln[2 * lane];
  __syncthreads();

  int row0 = blockIdx.x * 64 + wid * 8;
  #pragma unroll 1
  for (int rr = 0; rr < 8; rr++) {
    int row = row0 + rr;
    float2 cv = ((const float2*)ctx)[(size_t)row * 32 + lane];
    float2 o = matvec64(WoT, cv, lane);
    float2 pv = ((const float2*)prev)[(size_t)row * 32 + lane];
    o.x += boc.x + pv.x;
    o.y += boc.y + pv.y;

    float S1 = warp_sum(o.x + o.y);
    float S2 = warp_sum(o.x * o.x + o.y * o.y);
    float mu = S1 * (1.f / 64.f);
    float rstd = rsqrtf(S2 * (1.f / 64.f) - mu * mu + 1e-5f);
    float2 x;
    x.x = (o.x - mu) * rstd * g1c.x + b1lc.x;
    x.y = (o.y - mu) * rstd * g1c.y + b1lc.y;

    float2 hv = matvec64(W1T, x, lane);
    hv.x = fmaxf(hv.x + b1c.x, 0.f);
    hv.y = fmaxf(hv.y + b1c.y, 0.f);

    float2 f = matvec64(W2T, hv, lane);
    f.x += b2c.x + x.x;
    f.y += b2c.y + x.y;

    S1 = warp_sum(f.x + f.y);
    S2 = warp_sum(f.x * f.x + f.y * f.y);
    mu = S1 * (1.f / 64.f);
    rstd = rsqrtf(S2 * (1.f / 64.f) - mu * mu + 1e-5f);
    float2 res;
    res.x = (f.x - mu) * rstd * g2c.x + b2lc.x;
    res.y = (f.y - mu) * rstd * g2c.y + b2lc.y;
    ((float2*)out)[(size_t)row * 32 + lane] = res;
  }
}

// ---------------------------------------------------------------------------
extern "C" void kernel_launch(void* const* d_in, const int* in_sizes, int n_in,
                              void* d_out, int out_size) {
  (void)n_in;
  const float* q    = (const float*)d_in[0];
  const float* k    = (const float*)d_in[1];
  const float* prev = (const float*)d_in[2];
  const float* Wq   = (const float*)d_in[3];
  const float* bq   = (const float*)d_in[4];
  const float* Wk   = (const float*)d_in[5];
  const float* bk   = (const float*)d_in[6];
  const float* Wv   = (const float*)d_in[7];
  const float* bv   = (const float*)d_in[8];
  const float* Wo   = (const float*)d_in[9];
  const float* bo   = (const float*)d_in[10];
  const float* g1   = (const float*)d_in[11];
  const float* b1l  = (const float*)d_in[12];
  const float* W1   = (const float*)d_in[13];
  const float* b1   = (const float*)d_in[14];
  const float* W2   = (const float*)d_in[15];
  const float* b2   = (const float*)d_in[16];
  const float* g2   = (const float*)d_in[17];
  const float* b2l  = (const float*)d_in[18];

  int B = in_sizes[0] / (LSEQ * EDIM);   // 64
  int nrows = B * LSEQ;                  // 32768
  float* out = (float*)d_out;
  float* attn_out = out + (size_t)nrows * EDIM;
  (void)out_size;

  float *qh, *kh, *vh, *ctx;
  cudaGetSymbolAddress((void**)&qh, g_qh);
  cudaGetSymbolAddress((void**)&kh, g_kh);
  cudaGetSymbolAddress((void**)&vh, g_vh);
  cudaGetSymbolAddress((void**)&ctx, g_ctx);

  proj_kernel<<<dim3(nrows / 128, 3), 256>>>(q, k, Wq, bq, Wk, bk, Wv, bv,
                                             qh, kh, vh);

  int smem = 2 * 512 * 12 * 4;  // 49152 B
  cudaFuncSetAttribute(attn_kernel, cudaFuncAttributeMaxDynamicSharedMemorySize,
                       smem);
  attn_kernel<<<dim3(LSEQ / 16, B), 256, smem>>>(qh, kh, vh, ctx, attn_out);

  epi_kernel<<<nrows / 64, 256>>>(ctx, prev, Wo, bo, g1, b1l, W1, b1, W2, b2,
                                  g2, b2l, out);
}